// round 2
// baseline (speedup 1.0000x reference)
#include <cuda_runtime.h>

#define THREADS 256
#define BM 32
static constexpr int TSTEPS = 200;
using ull = unsigned long long;

// strides in ull (8-byte) units for duplicated-activation buffers
static constexpr int HD_STRIDE = 258;   // 256 cols + 2 pad  (row diff => +4 banks)
static constexpr int YD_STRIDE = 66;    // 64 cols + 2 pad

// smem layout (bytes)
static constexpr int OFF_W1  = 0;                          // W1: 64x256 f32
static constexpr int OFF_YD  = OFF_W1 + 64*256*4;          // y dup: 32 x 66 ull
static constexpr int OFF_H1D = OFF_YD + BM*YD_STRIDE*8;    // h1 dup: 32 x 258 ull
static constexpr int OFF_H2D = OFF_H1D + BM*HD_STRIDE*8;   // h2 dup
static constexpr int OFF_B1  = OFF_H2D + BM*HD_STRIDE*8;
static constexpr int OFF_B2  = OFF_B1 + 256*4;
static constexpr int OFF_B3  = OFF_B2 + 256*4;
static constexpr int SMEM_BYTES = OFF_B3 + 64*4;           // 216832 B

__device__ __forceinline__ ull dup2(float v) {
    ull r;
    asm("mov.b64 %0, {%1, %1};" : "=l"(r) : "r"(__float_as_uint(v)));
    return r;
}
__device__ __forceinline__ float2 unpk(ull p) {
    unsigned lo, hi;
    asm("mov.b64 {%0, %1}, %2;" : "=r"(lo), "=r"(hi) : "l"(p));
    return make_float2(__uint_as_float(lo), __uint_as_float(hi));
}
// d = a*b + d  (two independent fp32 FMAs in one instruction)
__device__ __forceinline__ void fma2(ull &d, ull a, ull b) {
    asm("fma.rn.f32x2 %0, %1, %2, %0;" : "+l"(d) : "l"(a), "l"(b));
}

__global__ void __launch_bounds__(THREADS, 1)
neural_ode_kernel(const float* __restrict__ y0,
                  const float* __restrict__ tarr,
                  const float* __restrict__ W1g,
                  const float* __restrict__ b1g,
                  const float* __restrict__ W2g,
                  const float* __restrict__ b2g,
                  const float* __restrict__ W3g,
                  const float* __restrict__ b3g,
                  float* __restrict__ out)
{
    extern __shared__ char smraw[];
    float* sW1 = (float*)(smraw + OFF_W1);
    ull*   yd  = (ull*)(smraw + OFF_YD);
    ull*   h1d = (ull*)(smraw + OFF_H1D);
    ull*   h2d = (ull*)(smraw + OFF_H2D);
    float* sb1 = (float*)(smraw + OFF_B1);
    float* sb2 = (float*)(smraw + OFF_B2);
    float* sb3 = (float*)(smraw + OFF_B3);

    const int tid  = threadIdx.x;
    const int row0 = blockIdx.x * BM;

    // one-time: W1 + biases into smem
    for (int i = tid; i < 64*256; i += THREADS) sW1[i] = W1g[i];
    if (tid < 256) { sb1[tid] = b1g[tid]; sb2[tid] = b2g[tid]; }
    if (tid < 64)  sb3[tid] = b3g[tid];

    // y0 tile -> duplicated smem, emit t=0 output slice
    for (int i = tid; i < BM*64; i += THREADS) {
        int r = i >> 6, d = i & 63;
        float v = y0[(size_t)(row0 + r)*64 + d];
        yd[r*YD_STRIDE + d] = dup2(v);
        out[((size_t)(row0 + r)*TSTEPS)*64 + d] = v;
    }
    const float dt = tarr[1] - tarr[0];
    __syncthreads();

    const int wid  = tid >> 5;
    const int lane = tid & 31;
    const int rg   = lane >> 3;                       // 0..3
    // GEMM1/2: warp tile 16 rows x 64 cols; thread 4 rows (stride 4) x 8 cols
    const int colA = (wid & 3)*64 + (lane & 7)*8;     // 8 cols: colA..colA+7
    const int rowA = (wid >> 2)*16 + rg;              // rows rowA + 4*r
    // GEMM3: warp tile 8 rows x 32 cols; thread 2 rows (stride 4) x 4 cols
    const int colC = (wid & 1)*32 + (lane & 7)*4;
    const int rowC = (wid >> 1)*8 + rg;               // rows rowC + 4*r

    for (int step = 1; step < TSTEPS; ++step) {
        // ================= GEMM1: h1 = relu(y @ W1 + b1), K=64 =================
        {
            ull acc[4][4];
            {
                ull b0 = *(const ull*)(sb1 + colA);
                ull b1v = *(const ull*)(sb1 + colA + 2);
                ull b2v = *(const ull*)(sb1 + colA + 4);
                ull b3v = *(const ull*)(sb1 + colA + 6);
                #pragma unroll
                for (int r = 0; r < 4; ++r) {
                    acc[r][0]=b0; acc[r][1]=b1v; acc[r][2]=b2v; acc[r][3]=b3v;
                }
            }
            #pragma unroll 4
            for (int k = 0; k < 64; k += 2) {
                ulonglong2 A0 = *(const ulonglong2*)(sW1 + k*256 + colA);
                ulonglong2 A1 = *(const ulonglong2*)(sW1 + k*256 + colA + 4);
                ulonglong2 B0 = *(const ulonglong2*)(sW1 + (k+1)*256 + colA);
                ulonglong2 B1 = *(const ulonglong2*)(sW1 + (k+1)*256 + colA + 4);
                #pragma unroll
                for (int r = 0; r < 4; ++r) {
                    ulonglong2 h = *(const ulonglong2*)(yd + (rowA + 4*r)*YD_STRIDE + k);
                    fma2(acc[r][0], h.x, A0.x); fma2(acc[r][1], h.x, A0.y);
                    fma2(acc[r][2], h.x, A1.x); fma2(acc[r][3], h.x, A1.y);
                    fma2(acc[r][0], h.y, B0.x); fma2(acc[r][1], h.y, B0.y);
                    fma2(acc[r][2], h.y, B1.x); fma2(acc[r][3], h.y, B1.y);
                }
            }
            #pragma unroll
            for (int r = 0; r < 4; ++r) {
                ull* dst = h1d + (rowA + 4*r)*HD_STRIDE + colA;
                #pragma unroll
                for (int p = 0; p < 4; ++p) {
                    float2 v = unpk(acc[r][p]);
                    ulonglong2 s;
                    s.x = dup2(fmaxf(v.x, 0.f));
                    s.y = dup2(fmaxf(v.y, 0.f));
                    *(ulonglong2*)(dst + 2*p) = s;
                }
            }
        }
        __syncthreads();

        // ================= GEMM2: h2 = relu(h1 @ W2 + b2), K=256 =================
        {
            ull acc[4][4];
            {
                ull b0 = *(const ull*)(sb2 + colA);
                ull b1v = *(const ull*)(sb2 + colA + 2);
                ull b2v = *(const ull*)(sb2 + colA + 4);
                ull b3v = *(const ull*)(sb2 + colA + 6);
                #pragma unroll
                for (int r = 0; r < 4; ++r) {
                    acc[r][0]=b0; acc[r][1]=b1v; acc[r][2]=b2v; acc[r][3]=b3v;
                }
            }
            const float* wb = W2g + colA;
            ulonglong2 nA0 = *(const ulonglong2*)(wb);
            ulonglong2 nA1 = *(const ulonglong2*)(wb + 4);
            ulonglong2 nB0 = *(const ulonglong2*)(wb + 256);
            ulonglong2 nB1 = *(const ulonglong2*)(wb + 260);
            #pragma unroll 4
            for (int k = 0; k < 256; k += 2) {
                ulonglong2 A0 = nA0, A1 = nA1, B0 = nB0, B1 = nB1;
                if (k + 2 < 256) {
                    const float* p = wb + (k + 2)*256;
                    nA0 = *(const ulonglong2*)(p);
                    nA1 = *(const ulonglong2*)(p + 4);
                    nB0 = *(const ulonglong2*)(p + 256);
                    nB1 = *(const ulonglong2*)(p + 260);
                }
                #pragma unroll
                for (int r = 0; r < 4; ++r) {
                    ulonglong2 h = *(const ulonglong2*)(h1d + (rowA + 4*r)*HD_STRIDE + k);
                    fma2(acc[r][0], h.x, A0.x); fma2(acc[r][1], h.x, A0.y);
                    fma2(acc[r][2], h.x, A1.x); fma2(acc[r][3], h.x, A1.y);
                    fma2(acc[r][0], h.y, B0.x); fma2(acc[r][1], h.y, B0.y);
                    fma2(acc[r][2], h.y, B1.x); fma2(acc[r][3], h.y, B1.y);
                }
            }
            #pragma unroll
            for (int r = 0; r < 4; ++r) {
                ull* dst = h2d + (rowA + 4*r)*HD_STRIDE + colA;
                #pragma unroll
                for (int p = 0; p < 4; ++p) {
                    float2 v = unpk(acc[r][p]);
                    ulonglong2 s;
                    s.x = dup2(fmaxf(v.x, 0.f));
                    s.y = dup2(fmaxf(v.y, 0.f));
                    *(ulonglong2*)(dst + 2*p) = s;
                }
            }
        }
        __syncthreads();

        // ================= GEMM3: y += dt*(h2 @ W3 + b3), K=256 =================
        {
            ull acc3[2][2];
            {
                ull b0 = *(const ull*)(sb3 + colC);
                ull b1v = *(const ull*)(sb3 + colC + 2);
                acc3[0][0]=b0; acc3[0][1]=b1v; acc3[1][0]=b0; acc3[1][1]=b1v;
            }
            const float* wb = W3g + colC;
            ulonglong2 nA = *(const ulonglong2*)(wb);
            ulonglong2 nB = *(const ulonglong2*)(wb + 64);
            #pragma unroll 4
            for (int k = 0; k < 256; k += 2) {
                ulonglong2 A = nA, B = nB;
                if (k + 2 < 256) {
                    const float* p = wb + (k + 2)*64;
                    nA = *(const ulonglong2*)(p);
                    nB = *(const ulonglong2*)(p + 64);
                }
                #pragma unroll
                for (int r = 0; r < 2; ++r) {
                    ulonglong2 h = *(const ulonglong2*)(h2d + (rowC + 4*r)*HD_STRIDE + k);
                    fma2(acc3[r][0], h.x, A.x); fma2(acc3[r][1], h.x, A.y);
                    fma2(acc3[r][0], h.y, B.x); fma2(acc3[r][1], h.y, B.y);
                }
            }
            #pragma unroll
            for (int r = 0; r < 2; ++r) {
                int row = rowC + 4*r;
                float2 a0 = unpk(acc3[r][0]);
                float2 a1 = unpk(acc3[r][1]);
                const float* yrow = (const float*)(yd + row*YD_STRIDE);
                float o0 = yrow[2*(colC+0)] + dt * a0.x;
                float o1 = yrow[2*(colC+1)] + dt * a0.y;
                float o2 = yrow[2*(colC+2)] + dt * a1.x;
                float o3 = yrow[2*(colC+3)] + dt * a1.y;
                ulonglong2 s0; s0.x = dup2(o0); s0.y = dup2(o1);
                ulonglong2 s1; s1.x = dup2(o2); s1.y = dup2(o3);
                *(ulonglong2*)(yd + row*YD_STRIDE + colC)     = s0;
                *(ulonglong2*)(yd + row*YD_STRIDE + colC + 2) = s1;
                float4 o = make_float4(o0, o1, o2, o3);
                *(float4*)(out + ((size_t)(row0 + row)*TSTEPS + step)*64 + colC) = o;
            }
        }
        __syncthreads();
    }
}

extern "C" void kernel_launch(void* const* d_in, const int* in_sizes, int n_in,
                              void* d_out, int out_size)
{
    const float* y0 = (const float*)d_in[0];
    const float* t  = (const float*)d_in[1];
    const float* W1 = (const float*)d_in[2];
    const float* b1 = (const float*)d_in[3];
    const float* W2 = (const float*)d_in[4];
    const float* b2 = (const float*)d_in[5];
    const float* W3 = (const float*)d_in[6];
    const float* b3 = (const float*)d_in[7];
    float* out = (float*)d_out;

    cudaFuncSetAttribute(neural_ode_kernel,
                         cudaFuncAttributeMaxDynamicSharedMemorySize,
                         SMEM_BYTES);

    int B = in_sizes[0] / 64;          // 4096
    int grid = B / BM;                 // 128
    neural_ode_kernel<<<grid, THREADS, SMEM_BYTES>>>(
        y0, t, W1, b1, W2, b2, W3, b3, out);
}